// round 3
// baseline (speedup 1.0000x reference)
#include <cuda_runtime.h>
#include <cstdint>

// Problem constants (fixed by setup_inputs)
#define BATCH 8
#define HEIGHT 720
#define WIDTH 1280
#define HW (HEIGHT * WIDTH)
#define EPSV 1e-6f
// log2(1.414)
#define LOG2_WB 0.49978216f

__device__ unsigned g_min_bits;

__device__ __forceinline__ unsigned f2key(float f) {
    unsigned b = __float_as_uint(f);
    return (b & 0x80000000u) ? ~b : (b | 0x80000000u);
}
__device__ __forceinline__ float key2f(unsigned k) {
    return (k & 0x80000000u) ? __uint_as_float(k & 0x7FFFFFFFu)
                             : __uint_as_float(~k);
}

__global__ void min_init_kernel() { g_min_bits = 0xFFFFFFFFu; }

__global__ void min_reduce_kernel(const float* __restrict__ disp, int n4) {
    const float4* p = (const float4*)disp;
    unsigned k = 0xFFFFFFFFu;
    for (int i = blockIdx.x * blockDim.x + threadIdx.x; i < n4;
         i += gridDim.x * blockDim.x) {
        float4 v = p[i];
        unsigned a = min(f2key(v.x), f2key(v.y));
        unsigned b = min(f2key(v.z), f2key(v.w));
        k = min(k, min(a, b));
    }
#pragma unroll
    for (int o = 16; o > 0; o >>= 1)
        k = min(k, __shfl_xor_sync(0xFFFFFFFFu, k, o));
    if ((threadIdx.x & 31) == 0) atomicMin(&g_min_bits, k);
}

// One CTA per (b, y) row. Shared-memory scatter-accumulate, then write out.
#define SPAD 8
#define SW (WIDTH + SPAD)

__global__ void __launch_bounds__(256) warp_row_kernel(
    const float* __restrict__ im, const float* __restrict__ disp,
    float* __restrict__ out) {
    __shared__ float s_r[SW];
    __shared__ float s_g[SW];
    __shared__ float s_b[SW];
    __shared__ float s_m[SW];
    __shared__ float s_o[SW];

    const int row = blockIdx.x;          // 0 .. B*H-1
    const int b = row / HEIGHT;
    const int y = row - b * HEIGHT;
    const int tid = threadIdx.x;

    for (int i = tid; i < SW; i += blockDim.x) {
        s_r[i] = 0.f; s_g[i] = 0.f; s_b[i] = 0.f; s_m[i] = 0.f; s_o[i] = 0.f;
    }
    __syncthreads();

    const float dmin = key2f(g_min_bits);

    const float* dr = disp + (size_t)(b * HEIGHT + y) * WIDTH;
    const float* ir = im + ((size_t)(b * 3 + 0) * HEIGHT + y) * WIDTH;
    const float* gr = im + ((size_t)(b * 3 + 1) * HEIGHT + y) * WIDTH;
    const float* br = im + ((size_t)(b * 3 + 2) * HEIGHT + y) * WIDTH;

#pragma unroll
    for (int it = 0; it < WIDTH / 256; it++) {
        const int x = it * 256 + tid;
        const float d = dr[x];
        const float wm = exp2f(LOG2_WB * (d - dmin));
        const float rv = ir[x];
        const float gv = gr[x];
        const float bv = br[x];

        const float fx = (float)x - d;       // target x; always < WIDTH
        const float x0f = floorf(fx);
        const int x0 = (int)x0f;
        const float w1 = fx - x0f;
        const float w0 = 1.0f - w1;

        // x0 <= x < WIDTH always; only left-edge check needed.
        if (x0 >= 0) {
            const float a = w0 * wm;
            atomicAdd(&s_r[x0], a * rv);
            atomicAdd(&s_g[x0], a * gv);
            atomicAdd(&s_b[x0], a * bv);
            atomicAdd(&s_m[x0], a);
            atomicAdd(&s_o[x0], w0);
        }
        const int x1 = x0 + 1;
        if (x1 >= 0 && x1 < WIDTH) {
            const float a = w1 * wm;
            atomicAdd(&s_r[x1], a * rv);
            atomicAdd(&s_g[x1], a * gv);
            atomicAdd(&s_b[x1], a * bv);
            atomicAdd(&s_m[x1], a);
            atomicAdd(&s_o[x1], w1);
        }
    }
    __syncthreads();

    // res: [B,3,H,W] at offset 0; occ: [B,1,H,W] at offset B*3*HW
    float* o_r = out + ((size_t)(b * 3 + 0) * HEIGHT + y) * WIDTH;
    float* o_g = out + ((size_t)(b * 3 + 1) * HEIGHT + y) * WIDTH;
    float* o_b = out + ((size_t)(b * 3 + 2) * HEIGHT + y) * WIDTH;
    float* o_o = out + (size_t)BATCH * 3 * HW + (size_t)(b * HEIGHT + y) * WIDTH;

#pragma unroll
    for (int it = 0; it < WIDTH / 256; it++) {
        const int x = it * 256 + tid;
        const float m = fmaxf(s_m[x], EPSV);
        const float inv = __frcp_rn(m);
        o_r[x] = s_r[x] * inv;
        o_g[x] = s_g[x] * inv;
        o_b[x] = s_b[x] * inv;
        o_o[x] = 1.0f - fminf(s_o[x], 1.0f);
    }
}

extern "C" void kernel_launch(void* const* d_in, const int* in_sizes, int n_in,
                              void* d_out, int out_size) {
    (void)in_sizes; (void)n_in; (void)out_size;
    const float* im = (const float*)d_in[0];
    const float* disp = (const float*)d_in[1];
    float* out = (float*)d_out;

    min_init_kernel<<<1, 1>>>();
    min_reduce_kernel<<<592, 256>>>(disp, (BATCH * HW) / 4);
    warp_row_kernel<<<BATCH * HEIGHT, 256>>>(im, disp, out);
}